// round 14
// baseline (speedup 1.0000x reference)
#include <cuda_runtime.h>
#include <cstdint>
#include <cstddef>

// Problem constants
#define BB   2
#define SS   1024
#define HID  2048
#define NH   32
#define NKV  4
#define DH   128
#define QKV_N 5120          // (32 + 2*4) * 128
#define CTX_N 4096          // 32 * 128
#define NTOK  2048          // B*S
#define ATT_SCALE 0.08838834764831845f   // 1/sqrt(128)
#define EPS  1e-6f

// Scratch (no cudaMalloc allowed)
__device__ float g_qkv[NTOK * QKV_N];      // 40 MiB (raw qkv, no norm)
__device__ float g_ctx[NTOK * CTX_N];      // 32 MiB
__device__ float g_wqkvT[QKV_N * HID];     // 40 MiB  (w_qkv^T, [N,K])
__device__ float g_woT[HID * CTX_N];       // 32 MiB  (w_o^T,   [N,K])

__device__ __forceinline__ uint32_t smem_u32(const void* p) {
    uint32_t a;
    asm("{ .reg .u64 t; cvta.to.shared.u64 t, %1; cvt.u32.u64 %0, t; }"
        : "=r"(a) : "l"(p));
    return a;
}

__device__ __forceinline__ float to_tf32(float x) {
    float r;
    asm("cvt.rna.tf32.f32 %0, %1;" : "=f"(r) : "f"(x));
    return r;
}

#define MMA_TF32(d0, d1, d2, d3, a0, a1, a2, a3, b0, b1)                        \
    asm volatile(                                                               \
        "mma.sync.aligned.m16n8k8.row.col.f32.tf32.tf32.f32 "                   \
        "{%0,%1,%2,%3}, {%4,%5,%6,%7}, {%8,%9}, {%0,%1,%2,%3};"                 \
        : "+f"(d0), "+f"(d1), "+f"(d2), "+f"(d3)                                \
        : "r"(a0), "r"(a1), "r"(a2), "r"(a3), "r"(b0), "r"(b1))

// ---------------------------------------------------------------------------
// 32x32 tiled transpose: dst[C,R] = src[R,C]^T   (R,C multiples of 32)
// ---------------------------------------------------------------------------
__global__ __launch_bounds__(256) void transpose32(const float* __restrict__ src,
                                                   float* __restrict__ dst,
                                                   int R, int C) {
    __shared__ float t[32][33];
    const int c0 = blockIdx.x * 32, r0 = blockIdx.y * 32;
    const int x = threadIdx.x & 31, y4 = (threadIdx.x >> 5) * 4;
#pragma unroll
    for (int i = 0; i < 4; i++)
        t[y4 + i][x] = src[(size_t)(r0 + y4 + i) * C + c0 + x];
    __syncthreads();
#pragma unroll
    for (int i = 0; i < 4; i++)
        dst[(size_t)(c0 + y4 + i) * R + r0 + x] = t[x][y4 + i];
}

// ---------------------------------------------------------------------------
// TF32 tensor-core GEMM via mma.sync (proven R7 version, unchanged):
//   C[M,N] = A[M,K] @ Bt[N,K]^T, fp32 in/out, RNA->tf32 on the smem path.
// ---------------------------------------------------------------------------
#define ABLK 132                 // words per (m16,k8) block (128 + 4 pad)
#define BBLK 66                  // words per (n8, k8) block (64 + 2 pad)
#define AW   (32 * ABLK)
#define BW   (64 * BBLK)
#define BUFW (AW + BW)
#define GM_SMEM_BYTES (2 * BUFW * 4)   // 67584 B

__global__ __launch_bounds__(256) void gemm_mma(const float* __restrict__ A,
                                                const float* __restrict__ Bt,
                                                float* __restrict__ C,
                                                int M, int N, int K) {
    extern __shared__ float sm[];
    const int tid = threadIdx.x, lane = tid & 31, wid = tid >> 5;
    const int wm = wid & 1, wn = wid >> 1;       // warp grid 2(m) x 4(n)
    const int m0 = blockIdx.x << 7, n0 = blockIdx.y << 7;

    const int k4 = tid & 7;                      // k = 4*k4 within 32-chunk
    const int r0 = tid >> 3;                     // 0..31
    const int k8 = k4 >> 1, khalf = k4 & 1;

    const float* Ag = A + (size_t)(m0 + r0) * K + k4 * 4;
    const float* Bg = Bt + (size_t)(n0 + r0) * K + k4 * 4;

    float4 ra[4], rb[4];
    float d[4][4][4];
#pragma unroll
    for (int mt = 0; mt < 4; mt++)
#pragma unroll
        for (int nt = 0; nt < 4; nt++)
#pragma unroll
            for (int j = 0; j < 4; j++) d[mt][nt][j] = 0.f;

    const int KT = K >> 5;
    const uint32_t sbase = smem_u32(sm);

#pragma unroll
    for (int i = 0; i < 4; i++) {
        ra[i] = *(const float4*)(Ag + (size_t)(i * 32) * K);
        rb[i] = *(const float4*)(Bg + (size_t)(i * 32) * K);
    }
    {
        float* sA = sm;
        float* sB = sm + AW;
#pragma unroll
        for (int i = 0; i < 4; i++) {
            const int m = i * 32 + r0;
            float* p = sA + ((m >> 4) * 4 + k8) * ABLK
                          + (m & 7) * 16 + ((m >> 3) & 1) + 2 * khalf;
            p[0]  = to_tf32(ra[i].x);
            p[4]  = to_tf32(ra[i].y);
            p[8]  = to_tf32(ra[i].z);
            p[12] = to_tf32(ra[i].w);
            float* q = sB + ((m >> 3) * 4 + k8) * BBLK + (m & 7) * 8 + khalf;
            q[0] = to_tf32(rb[i].x);
            q[2] = to_tf32(rb[i].y);
            q[4] = to_tf32(rb[i].z);
            q[6] = to_tf32(rb[i].w);
        }
    }
    __syncthreads();

    for (int kt = 0; kt < KT; ++kt) {
        const int cur = kt & 1;
        const bool more = (kt + 1 < KT);
        if (more) {
            const size_t koff = (size_t)(kt + 1) * 32;
#pragma unroll
            for (int i = 0; i < 4; i++) {
                ra[i] = *(const float4*)(Ag + (size_t)(i * 32) * K + koff);
                rb[i] = *(const float4*)(Bg + (size_t)(i * 32) * K + koff);
            }
        }

        {
            const uint32_t aB = sbase + (uint32_t)(cur * BUFW) * 4;
            const uint32_t bB = aB + AW * 4;
#pragma unroll
            for (int kk = 0; kk < 4; ++kk) {
                uint32_t af[4][4], bf[4][2];
#pragma unroll
                for (int mt = 0; mt < 4; mt++) {
                    uint32_t addr = aB + (uint32_t)((((wm * 4 + mt) * 4 + kk) * ABLK
                                                    + lane * 4) * 4);
                    asm volatile("ld.shared.v4.b32 {%0,%1,%2,%3}, [%4];"
                                 : "=r"(af[mt][0]), "=r"(af[mt][1]),
                                   "=r"(af[mt][2]), "=r"(af[mt][3])
                                 : "r"(addr));
                }
#pragma unroll
                for (int nt = 0; nt < 4; nt++) {
                    uint32_t addr = bB + (uint32_t)((((wn * 4 + nt) * 4 + kk) * BBLK
                                                    + lane * 2) * 4);
                    asm volatile("ld.shared.v2.b32 {%0,%1}, [%2];"
                                 : "=r"(bf[nt][0]), "=r"(bf[nt][1])
                                 : "r"(addr));
                }
#pragma unroll
                for (int mt = 0; mt < 4; mt++)
#pragma unroll
                    for (int nt = 0; nt < 4; nt++)
                        MMA_TF32(d[mt][nt][0], d[mt][nt][1], d[mt][nt][2], d[mt][nt][3],
                                 af[mt][0], af[mt][1], af[mt][2], af[mt][3],
                                 bf[nt][0], bf[nt][1]);
            }
        }

        if (more) {
            float* sA = sm + (cur ^ 1) * BUFW;
            float* sB = sA + AW;
#pragma unroll
            for (int i = 0; i < 4; i++) {
                const int m = i * 32 + r0;
                float* p = sA + ((m >> 4) * 4 + k8) * ABLK
                              + (m & 7) * 16 + ((m >> 3) & 1) + 2 * khalf;
                p[0]  = to_tf32(ra[i].x);
                p[4]  = to_tf32(ra[i].y);
                p[8]  = to_tf32(ra[i].z);
                p[12] = to_tf32(ra[i].w);
                float* q = sB + ((m >> 3) * 4 + k8) * BBLK + (m & 7) * 8 + khalf;
                q[0] = to_tf32(rb[i].x);
                q[2] = to_tf32(rb[i].y);
                q[4] = to_tf32(rb[i].z);
                q[6] = to_tf32(rb[i].w);
            }
        }
        __syncthreads();
    }

    const int g = lane >> 2, t = lane & 3;
#pragma unroll
    for (int mt = 0; mt < 4; mt++) {
        const int row = m0 + wm * 64 + mt * 16 + g;
#pragma unroll
        for (int nt = 0; nt < 4; nt++) {
            const int col = n0 + wn * 32 + nt * 8 + t * 2;
            *(float2*)&C[(size_t)row * N + col] =
                make_float2(d[mt][nt][0], d[mt][nt][1]);
            *(float2*)&C[(size_t)(row + 8) * N + col] =
                make_float2(d[mt][nt][2], d[mt][nt][3]);
        }
    }
}

// ---------------------------------------------------------------------------
// Tensor-core flash attention with FUSED per-head RMSNorm + RoPE on Q/K.
// CTA = (q-tile 128, head, batch), 8 warps. Q fragments held in REGISTERS
// (loaded once via a bounce through smem); the freed Qa region doubles as the
// second K/V buffer -> double-buffered staging, ONE __syncthreads per tile.
// Fragment layouts identical to gemm_mma (A: 132-word blocks, B: 66).
// ---------------------------------------------------------------------------
#define AT_QA_W (8 * 16 * ABLK)     // 16896 words = 67584 B (Q stage / KV buf 1)
#define AT_KV_W (8 * 16 * BBLK + 16 * 8 * BBLK)   // 16896 words (K + V one buf)
#define AT_PA_W (8 * 8 * ABLK)      //  8448
#define AT_SMEM_BYTES ((AT_QA_W + AT_KV_W + AT_PA_W) * 4)  // 168960

// Stage one 64-key K/V tile into fragment layout, applying RMSNorm(kw)+RoPE
// to K on the fly. Warp per row; lane holds d = 4*lane .. 4*lane+3.
__device__ __forceinline__ void stage_kv(
    const float* __restrict__ qkv, float* __restrict__ Kb, float* __restrict__ Vb,
    int rowbase, int kbase, int kcol, int vcol,
    const float* __restrict__ kw,
    const float* __restrict__ cosT, const float* __restrict__ sinT,
    int wid, int lane) {
    const float sgn = (lane < 16) ? -1.f : 1.f;
#pragma unroll
    for (int i = 0; i < 8; i++) {
        const int row = i * 8 + wid;               // 0..63
        const int s = kbase + row;                 // seq position
        const float* src = &qkv[(size_t)(rowbase + s) * QKV_N];
        float4 kv = *(const float4*)(src + kcol + lane * 4);
        float4 vv = *(const float4*)(src + vcol + lane * 4);
        // RMSNorm over the row
        float sq = kv.x * kv.x + kv.y * kv.y + kv.z * kv.z + kv.w * kv.w;
#pragma unroll
        for (int o = 16; o; o >>= 1) sq += __shfl_xor_sync(0xffffffffu, sq, o);
        const float r = rsqrtf(sq * (1.f / DH) + EPS);
        float4 w4 = *(const float4*)&kw[lane * 4];
        float x0 = kv.x * r * w4.x, x1 = kv.y * r * w4.y;
        float x2 = kv.z * r * w4.z, x3 = kv.w * r * w4.w;
        // RoPE: partner lane^16 holds d +/- 64
        float y0 = __shfl_xor_sync(0xffffffffu, x0, 16);
        float y1 = __shfl_xor_sync(0xffffffffu, x1, 16);
        float y2 = __shfl_xor_sync(0xffffffffu, x2, 16);
        float y3 = __shfl_xor_sync(0xffffffffu, x3, 16);
        float4 c = *(const float4*)&cosT[(size_t)s * DH + lane * 4];
        float4 sn = *(const float4*)&sinT[(size_t)s * DH + lane * 4];
        x0 = x0 * c.x + sgn * y0 * sn.x;
        x1 = x1 * c.y + sgn * y1 * sn.y;
        x2 = x2 * c.z + sgn * y2 * sn.z;
        x3 = x3 * c.w + sgn * y3 * sn.w;
        // scatter K (B-layout: n=row, k=4*lane+j)
        float* p = Kb + ((row >> 3) * 16 + (lane >> 1)) * BBLK
                      + (row & 7) * 8 + (lane & 1);
        p[0] = to_tf32(x0);
        p[2] = to_tf32(x1);
        p[4] = to_tf32(x2);
        p[6] = to_tf32(x3);
        // scatter V (B-layout: n=4*lane+j, k=row)
        float* q = Vb + ((lane >> 1) * 8 + (row >> 3)) * BBLK
                      + (lane & 1) * 32 + (row & 3) * 2 + ((row >> 2) & 1);
        q[0]  = to_tf32(vv.x);
        q[8]  = to_tf32(vv.y);
        q[16] = to_tf32(vv.z);
        q[24] = to_tf32(vv.w);
    }
}

__global__ __launch_bounds__(256) void attn_tc(const float* __restrict__ qkv,
                                               float* __restrict__ ctx,
                                               const float* __restrict__ qw,
                                               const float* __restrict__ kw,
                                               const float* __restrict__ cosT,
                                               const float* __restrict__ sinT) {
    extern __shared__ float sm[];
    // buffers: buf1 region (also Q staging) | buf0 region | Pa
    float* Kb1 = sm;                       // 8448 w
    float* Vb1 = sm + 8 * 16 * BBLK;       // 8448 w   (Kb1+Vb1 == Qa region)
    float* Kb0 = sm + AT_QA_W;
    float* Vb0 = Kb0 + 8 * 16 * BBLK;
    float* Pa  = sm + AT_QA_W + AT_KV_W;
    float* Qa  = sm;                       // Q staging aliases buf1
    const uint32_t qa_u = smem_u32(Qa), pa_u = smem_u32(Pa);
    const uint32_t kb_u[2] = {smem_u32(Kb0), smem_u32(Kb1)};
    const uint32_t vb_u[2] = {smem_u32(Vb0), smem_u32(Vb1)};
    float* KbA[2] = {Kb0, Kb1};
    float* VbA[2] = {Vb0, Vb1};

    const int qt = (int)gridDim.x - 1 - (int)blockIdx.x;   // heavy tiles first
    const int h = blockIdx.y, b = blockIdx.z;
    const int kh = h >> 3;
    const int tid = threadIdx.x, lane = tid & 31, wid = tid >> 5;
    const int g = lane >> 2, t = lane & 3;
    const int rowbase = b * SS, qbase = qt * 128;
    const int qcol = h * DH;
    const int kcol = NH * DH + kh * DH;
    const int vcol = (NH + NKV) * DH + kh * DH;
    const float sgn = (lane < 16) ? -1.f : 1.f;

    // ---- stage Q tile (norm+rope fused) into Qa (A-fragment layout) ----
#pragma unroll
    for (int i = 0; i < 16; i++) {
        const int row = i * 8 + wid;               // 0..127
        const int s = qbase + row;
        float4 v = *(const float4*)&qkv[(size_t)(rowbase + s) * QKV_N
                                        + qcol + lane * 4];
        float sq = v.x * v.x + v.y * v.y + v.z * v.z + v.w * v.w;
#pragma unroll
        for (int o = 16; o; o >>= 1) sq += __shfl_xor_sync(0xffffffffu, sq, o);
        const float r = rsqrtf(sq * (1.f / DH) + EPS);
        float4 w4 = *(const float4*)&qw[lane * 4];
        float x0 = v.x * r * w4.x, x1 = v.y * r * w4.y;
        float x2 = v.z * r * w4.z, x3 = v.w * r * w4.w;
        float y0 = __shfl_xor_sync(0xffffffffu, x0, 16);
        float y1 = __shfl_xor_sync(0xffffffffu, x1, 16);
        float y2 = __shfl_xor_sync(0xffffffffu, x2, 16);
        float y3 = __shfl_xor_sync(0xffffffffu, x3, 16);
        float4 c = *(const float4*)&cosT[(size_t)s * DH + lane * 4];
        float4 sn = *(const float4*)&sinT[(size_t)s * DH + lane * 4];
        x0 = x0 * c.x + sgn * y0 * sn.x;
        x1 = x1 * c.y + sgn * y1 * sn.y;
        x2 = x2 * c.z + sgn * y2 * sn.z;
        x3 = x3 * c.w + sgn * y3 * sn.w;
        float* p = Qa + ((row >> 4) * 16 + (lane >> 1)) * ABLK
                      + (row & 7) * 16 + ((row >> 3) & 1) + 2 * (lane & 1);
        p[0]  = to_tf32(x0);
        p[4]  = to_tf32(x1);
        p[8]  = to_tf32(x2);
        p[12] = to_tf32(x3);
    }
    __syncthreads();

    // ---- load this warp's Q fragments into registers (once) ----
    uint32_t Qr[16][4];
#pragma unroll
    for (int kk = 0; kk < 16; ++kk) {
        uint32_t addr = qa_u + (uint32_t)(((wid * 16 + kk) * ABLK + lane * 4) * 4);
        asm volatile("ld.shared.v4.b32 {%0,%1,%2,%3}, [%4];"
                     : "=r"(Qr[kk][0]), "=r"(Qr[kk][1]),
                       "=r"(Qr[kk][2]), "=r"(Qr[kk][3])
                     : "r"(addr));
    }
    __syncthreads();   // everyone done reading Qa before it becomes buf1

    // ---- prologue: stage tile 0 into buf0 ----
    stage_kv(qkv, Kb0, Vb0, rowbase, 0, kcol, vcol, kw, cosT, sinT, wid, lane);
    __syncthreads();

    float o[16][4];
#pragma unroll
    for (int dn = 0; dn < 16; dn++)
#pragma unroll
        for (int j = 0; j < 4; j++) o[dn][j] = 0.f;
    float m0 = -1e30f, m1 = -1e30f, l0 = 0.f, l1 = 0.f;

    const int qrow0 = qbase + wid * 16 + g;
    const int qrow1 = qrow0 + 8;
    const int ktn = 2 * qt + 2;

    for (int kt = 0; kt < ktn; ++kt) {
        const int cur = (kt & 1) ^ 0;   // kt=0 -> buf0
        const int kbase = kt * 64;
        const uint32_t kbu = kb_u[kt & 1 ? 1 : 0];
        const uint32_t vbu = vb_u[kt & 1 ? 1 : 0];

        // ---- S = Q @ K^T  (warp: 16 q-rows x 64 keys), Q from registers ----
        float s[8][4];
#pragma unroll
        for (int nt = 0; nt < 8; nt++)
#pragma unroll
            for (int j = 0; j < 4; j++) s[nt][j] = 0.f;

#pragma unroll
        for (int kk = 0; kk < 16; ++kk) {
#pragma unroll
            for (int nt = 0; nt < 8; nt++) {
                uint32_t bf[2];
                uint32_t baddr = kbu + (uint32_t)(((nt * 16 + kk) * BBLK + lane * 2) * 4);
                asm volatile("ld.shared.v2.b32 {%0,%1}, [%2];"
                             : "=r"(bf[0]), "=r"(bf[1]) : "r"(baddr));
                MMA_TF32(s[nt][0], s[nt][1], s[nt][2], s[nt][3],
                         Qr[kk][0], Qr[kk][1], Qr[kk][2], Qr[kk][3],
                         bf[0], bf[1]);
            }
        }

        // ---- online softmax ----
        const bool domask = (kt >= 2 * qt);
        float vmax0 = -1e30f, vmax1 = -1e30f;
#pragma unroll
        for (int nt = 0; nt < 8; nt++) {
            int c = kbase + nt * 8 + t * 2;
            float v0 = s[nt][0] * ATT_SCALE, v1 = s[nt][1] * ATT_SCALE;
            float v2 = s[nt][2] * ATT_SCALE, v3 = s[nt][3] * ATT_SCALE;
            if (domask) {
                if (c > qrow0)     v0 = -1e30f;
                if (c + 1 > qrow0) v1 = -1e30f;
                if (c > qrow1)     v2 = -1e30f;
                if (c + 1 > qrow1) v3 = -1e30f;
            }
            s[nt][0] = v0; s[nt][1] = v1; s[nt][2] = v2; s[nt][3] = v3;
            vmax0 = fmaxf(vmax0, fmaxf(v0, v1));
            vmax1 = fmaxf(vmax1, fmaxf(v2, v3));
        }
        vmax0 = fmaxf(vmax0, __shfl_xor_sync(0xffffffffu, vmax0, 1));
        vmax0 = fmaxf(vmax0, __shfl_xor_sync(0xffffffffu, vmax0, 2));
        vmax1 = fmaxf(vmax1, __shfl_xor_sync(0xffffffffu, vmax1, 1));
        vmax1 = fmaxf(vmax1, __shfl_xor_sync(0xffffffffu, vmax1, 2));

        float m0n = fmaxf(m0, vmax0), m1n = fmaxf(m1, vmax1);
        float a0 = __expf(m0 - m0n), a1 = __expf(m1 - m1n);
        float sum0 = 0.f, sum1 = 0.f;

        const int offA = 4 * ((2 * t) & 3) + 2 * (((2 * t) >> 2) & 1);
        const int offB = 4 * ((2 * t + 1) & 3) + 2 * (((2 * t + 1) >> 2) & 1);
#pragma unroll
        for (int nt = 0; nt < 8; nt++) {
            float p0 = __expf(s[nt][0] - m0n);
            float p1 = __expf(s[nt][1] - m0n);
            float p2 = __expf(s[nt][2] - m1n);
            float p3 = __expf(s[nt][3] - m1n);
            sum0 += p0 + p1;
            sum1 += p2 + p3;
            float* base = Pa + (wid * 8 + nt) * ABLK + 16 * g;
            base[offA]     = to_tf32(p0);
            base[offB]     = to_tf32(p1);
            base[offA + 1] = to_tf32(p2);
            base[offB + 1] = to_tf32(p3);
        }
        sum0 += __shfl_xor_sync(0xffffffffu, sum0, 1);
        sum0 += __shfl_xor_sync(0xffffffffu, sum0, 2);
        sum1 += __shfl_xor_sync(0xffffffffu, sum1, 1);
        sum1 += __shfl_xor_sync(0xffffffffu, sum1, 2);

        m0 = m0n; m1 = m1n;
        l0 = l0 * a0 + sum0;
        l1 = l1 * a1 + sum1;
#pragma unroll
        for (int dn = 0; dn < 16; dn++) {
            o[dn][0] *= a0; o[dn][1] *= a0;
            o[dn][2] *= a1; o[dn][3] *= a1;
        }
        __syncwarp();

        // ---- stage NEXT K/V tile into the other buffer (overlaps PV) ----
        if (kt + 1 < ktn) {
            const int nb = (kt + 1) & 1;
            stage_kv(qkv, KbA[nb], VbA[nb], rowbase, (kt + 1) * 64,
                     kcol, vcol, kw, cosT, sinT, wid, lane);
        }

        // ---- O += P @ V  (warp: 16 q-rows x 128 d) ----
#pragma unroll
        for (int kk = 0; kk < 8; ++kk) {
            uint32_t af[4];
            uint32_t aaddr = pa_u + (uint32_t)(((wid * 8 + kk) * ABLK + lane * 4) * 4);
            asm volatile("ld.shared.v4.b32 {%0,%1,%2,%3}, [%4];"
                         : "=r"(af[0]), "=r"(af[1]), "=r"(af[2]), "=r"(af[3])
                         : "r"(aaddr));
#pragma unroll
            for (int dn = 0; dn < 16; dn++) {
                uint32_t bf[2];
                uint32_t baddr = vbu + (uint32_t)(((dn * 8 + kk) * BBLK + lane * 2) * 4);
                asm volatile("ld.shared.v2.b32 {%0,%1}, [%2];"
                             : "=r"(bf[0]), "=r"(bf[1]) : "r"(baddr));
                MMA_TF32(o[dn][0], o[dn][1], o[dn][2], o[dn][3],
                         af[0], af[1], af[2], af[3], bf[0], bf[1]);
            }
        }
        __syncthreads();   // staging(kt+1) complete; all readers of cur done
        (void)cur;
    }

    // ---- epilogue: O /= l, write ctx ----
    const float il0 = 1.f / l0, il1 = 1.f / l1;
    const int row0 = rowbase + qrow0;
#pragma unroll
    for (int dn = 0; dn < 16; dn++) {
        const int col = h * DH + dn * 8 + t * 2;
        *(float2*)&ctx[(size_t)row0 * CTX_N + col] =
            make_float2(o[dn][0] * il0, o[dn][1] * il0);
        *(float2*)&ctx[(size_t)(row0 + 8) * CTX_N + col] =
            make_float2(o[dn][2] * il1, o[dn][3] * il1);
    }
}

// ---------------------------------------------------------------------------
extern "C" void kernel_launch(void* const* d_in, const int* in_sizes, int n_in,
                              void* d_out, int out_size) {
    const float* hidden = (const float*)d_in[0];   // [B,S,HID]
    const float* cosT   = (const float*)d_in[1];   // [1,S,1,D]
    const float* sinT   = (const float*)d_in[2];
    const float* w_qkv  = (const float*)d_in[3];   // [HID, 5120]
    const float* qw     = (const float*)d_in[4];   // [128]
    const float* kw     = (const float*)d_in[5];   // [128]
    const float* w_o    = (const float*)d_in[6];   // [4096, HID]
    float* out = (float*)d_out;                    // [B,S,HID]

    float *qkv, *ctx, *wqkvT, *woT;
    cudaGetSymbolAddress((void**)&qkv,   g_qkv);
    cudaGetSymbolAddress((void**)&ctx,   g_ctx);
    cudaGetSymbolAddress((void**)&wqkvT, g_wqkvT);
    cudaGetSymbolAddress((void**)&woT,   g_woT);

    cudaFuncSetAttribute(gemm_mma, cudaFuncAttributeMaxDynamicSharedMemorySize,
                         GM_SMEM_BYTES);
    cudaFuncSetAttribute(attn_tc, cudaFuncAttributeMaxDynamicSharedMemorySize,
                         AT_SMEM_BYTES);

    // 0) Weight transposes to [N,K] for K-major B operand
    transpose32<<<dim3(QKV_N / 32, HID / 32), 256>>>(w_qkv, wqkvT, HID, QKV_N);
    transpose32<<<dim3(HID / 32, CTX_N / 32), 256>>>(w_o, woT, CTX_N, HID);

    // 1) QKV projection (mma.sync tf32): [2048,2048] @ [2048,5120]
    gemm_mma<<<dim3(NTOK / 128, QKV_N / 128), 256, GM_SMEM_BYTES>>>(
        hidden, wqkvT, qkv, NTOK, QKV_N, HID);

    // 2+3) Causal GQA flash attention with fused RMSNorm + RoPE (mma.sync tf32)
    attn_tc<<<dim3(SS / 128, NH, BB), 256, AT_SMEM_BYTES>>>(
        qkv, ctx, qw, kw, cosT, sinT);

    // 4) Output projection (mma.sync tf32): [2048,4096] @ [4096,2048]
    gemm_mma<<<dim3(NTOK / 128, HID / 128), 256, GM_SMEM_BYTES>>>(
        ctx, woT, out, NTOK, HID, CTX_N);
}